// round 14
// baseline (speedup 1.0000x reference)
#include <cuda_runtime.h>
#include <cuda_fp16.h>
#include <stdint.h>
#include <math.h>

static constexpr int BATCH  = 16;
static constexpr int C      = 128;
static constexpr int N      = 16384;
static constexpr int SPLITK = 16;
static constexpr int CHUNK  = N / SPLITK;    // 1024
static constexpr int NTILES = N / 128;       // 128
static constexpr size_t OUT_ELEMS = (size_t)BATCH * C * N;
static constexpr int LDS_ = 136;             // padded smem stride (uint32 words)

// ---------------- scratch (static device globals; no allocations) ----------
__device__ __half g_kg [(size_t)BATCH * C * N];          // fp16
__device__ __half g_v  [(size_t)BATCH * C * N];          // fp16
__device__ float g_part[(size_t)BATCH * SPLITK * C * C];
__device__ float g_fsum[(size_t)BATCH * NTILES * C];     // [b][tile][c]
__device__ float g_E   [(size_t)BATCH * C * C];
__device__ float g_F   [(size_t)BATCH * C * C];
__device__ float g_fb  [(size_t)BATCH * C];

__device__ __forceinline__ float sigmoidf_(float v) { return 1.0f / (1.0f + __expf(-v)); }
__device__ __forceinline__ uint32_t pk2(float a, float b) {
    __half2 h = __floats2half2_rn(a, b);
    return *(uint32_t*)&h;
}

// m16n8k16 f16 mma, fp32 accumulate.
__device__ __forceinline__ void mma_f16(float c[4],
    uint32_t a0, uint32_t a1, uint32_t a2, uint32_t a3, uint32_t b0, uint32_t b1)
{
    asm volatile(
        "mma.sync.aligned.m16n8k16.row.col.f32.f16.f16.f32 "
        "{%0,%1,%2,%3}, {%4,%5,%6,%7}, {%8,%9}, {%0,%1,%2,%3};\n"
        : "+f"(c[0]), "+f"(c[1]), "+f"(c[2]), "+f"(c[3])
        : "r"(a0), "r"(a1), "r"(a2), "r"(a3), "r"(b0), "r"(b1));
}

// ---- 32-K slab loaders (smem = 16 half2-rows x 128) ------------------------
// A transpose (cvt): thread owns row m = tid>>1, k2-range = (tid&1)*8..+8.
// Caller passes p = row_base + kk + ((tid&1)<<4)  (16 floats).
__device__ __forceinline__ void stsT_h(uint32_t (*S)[LDS_], const float* p, int tid) {
    const int m = tid >> 1, ko = (tid & 1) << 3;
    float4 u0 = *(const float4*)(p);
    float4 u1 = *(const float4*)(p + 4);
    float4 u2 = *(const float4*)(p + 8);
    float4 u3 = *(const float4*)(p + 12);
    S[ko + 0][m] = pk2(u0.x, u0.y); S[ko + 1][m] = pk2(u0.z, u0.w);
    S[ko + 2][m] = pk2(u1.x, u1.y); S[ko + 3][m] = pk2(u1.z, u1.w);
    S[ko + 4][m] = pk2(u2.x, u2.y); S[ko + 5][m] = pk2(u2.z, u2.w);
    S[ko + 6][m] = pk2(u3.x, u3.y); S[ko + 7][m] = pk2(u3.z, u3.w);
}
// A transpose (raw half): p = row_base + ss*32 + ((tid&1)<<4)  (16 halves).
__device__ __forceinline__ void stsT_raw_h(uint32_t (*S)[LDS_], const __half* p, int tid) {
    const int m = tid >> 1, ko = (tid & 1) << 3;
    uint4 a = *(const uint4*)(p);
    uint4 b = *(const uint4*)(p + 8);
    S[ko + 0][m] = a.x; S[ko + 1][m] = a.y; S[ko + 2][m] = a.z; S[ko + 3][m] = a.w;
    S[ko + 4][m] = b.x; S[ko + 5][m] = b.y; S[ko + 6][m] = b.z; S[ko + 7][m] = b.w;
}
// B direct (cvt): packs rows (2kb, 2kb+1) into half2; src = base at (row kk, col n0).
__device__ __forceinline__ void stsD_h(uint32_t (*S)[LDS_], const float* src, size_t ld, int tid) {
    const int kb = tid >> 4, nb = (tid & 15) << 3;
    const float* r0 = src + (size_t)(2 * kb) * ld + nb;
    const float* r1 = r0 + ld;
    float4 a0 = *(const float4*)r0, a1 = *(const float4*)(r0 + 4);
    float4 b0 = *(const float4*)r1, b1 = *(const float4*)(r1 + 4);
    *(uint4*)&S[kb][nb]     = make_uint4(pk2(a0.x, b0.x), pk2(a0.y, b0.y),
                                         pk2(a0.z, b0.z), pk2(a0.w, b0.w));
    *(uint4*)&S[kb][nb + 4] = make_uint4(pk2(a1.x, b1.x), pk2(a1.y, b1.y),
                                         pk2(a1.z, b1.z), pk2(a1.w, b1.w));
}

// One 32-K slab (16 half2-rows), warp tile 64x32 (4 mf x 4 nf), 2 mma rounds.
// Frag maps (m16n8k16 f16): a0(g,k2=tig) a1(g+8,tig) a2(g,tig+4) a3(g+8,tig+4);
// b0(k2=tig,n) b1(tig+4,n); c0(g,2tig) c1(g,2tig+1) c2(g+8,2tig) c3(g+8,2tig+1).
__device__ __forceinline__ void compute_slab_h(const uint32_t (*As)[LDS_], const uint32_t (*Bs)[LDS_],
                                               float acc[4][4][4], int mrow, int ncol, int g, int tig)
{
#pragma unroll
    for (int ks = 0; ks < 2; ks++) {
        uint32_t a[4][4], b[4][2];
#pragma unroll
        for (int mf = 0; mf < 4; mf++) {
            const int m = mrow + mf * 16 + g;
            a[mf][0] = As[ks * 8 + tig][m];     a[mf][1] = As[ks * 8 + tig][m + 8];
            a[mf][2] = As[ks * 8 + tig + 4][m]; a[mf][3] = As[ks * 8 + tig + 4][m + 8];
        }
#pragma unroll
        for (int nf = 0; nf < 4; nf++) {
            const int n = ncol + nf * 8 + g;
            b[nf][0] = Bs[ks * 8 + tig][n]; b[nf][1] = Bs[ks * 8 + tig + 4][n];
        }
#pragma unroll
        for (int mf = 0; mf < 4; mf++)
#pragma unroll
            for (int nf = 0; nf < 4; nf++)
                mma_f16(acc[mf][nf], a[mf][0], a[mf][1], a[mf][2], a[mf][3],
                        b[nf][0], b[nf][1]);
    }
}

// ---------------------------------------------------------------------------
// Kernel 1: fused projections (fp16 tensor cores). R7 structure.
// Virtual A rows: 16-row group = 8 channels' value rows (0-7) + same channels'
// gate rows (8-15) -> value in c0/c1, gate in c2/c3 of the SAME thread.
// ---------------------------------------------------------------------------
__global__ void __launch_bounds__(256, 2)
proj_h(const float* __restrict__ x,
       const float* __restrict__ Wk, const float* __restrict__ bk,
       const float* __restrict__ Wv, const float* __restrict__ bv,
       const float* __restrict__ Wg, const float* __restrict__ bg)
{
    __shared__ uint32_t As[16][LDS_];
    __shared__ uint32_t Bs[16][LDS_];
    __shared__ float red[64][4];

    const int idx   = blockIdx.x;
    const int type  = idx >> 1;
    const int cbase = (idx & 1) * 64;
    const int n0    = blockIdx.y << 7;
    const int b     = blockIdx.z;

    const float *W1, *W2, *b1, *b2;
    if (type == 0) { W1 = Wk; b1 = bk; W2 = Wg + C * C; b2 = bg + C; }   // k / input gate
    else           { W1 = Wv; b1 = bv; W2 = Wg;         b2 = bg;     }   // v / forget gate

    const int tid = threadIdx.x, lane = tid & 31, warp = tid >> 5;
    const int g = lane >> 2, tig = lane & 3;
    const int warpM = warp & 1, warpN = warp >> 1;
    const int mrow = warpM * 64, ncol = warpN * 32;

    const int am = tid >> 1;
    const int agrp = am >> 4, awi = am & 15;
    const int ach = cbase + agrp * 8 + (awi & 7);
    const float* myArow = ((awi < 8) ? W1 : W2) + (size_t)ach * C;
    const float* xb = x + (size_t)b * C * N;

    float acc[4][4][4] = {};
#pragma unroll 1
    for (int kk = 0; kk < C; kk += 32) {
        stsT_h(As, myArow + kk + ((tid & 1) << 4), tid);
        stsD_h(Bs, xb + (size_t)kk * N + n0, N, tid);
        __syncthreads();
        compute_slab_h(As, Bs, acc, mrow, ncol, g, tig);
        __syncthreads();
    }

    if (type == 0) {
#pragma unroll
        for (int mf = 0; mf < 4; mf++) {
            const int ch = cbase + (warpM * 4 + mf) * 8 + g;
            const float bb1 = b1[ch], bb2 = b2[ch];
            __half* dst = g_kg + ((size_t)b * C + ch) * N + n0 + ncol + 2 * tig;
#pragma unroll
            for (int nf = 0; nf < 4; nf++) {
                float o0 = (acc[mf][nf][0] + bb1) * sigmoidf_(acc[mf][nf][2] + bb2);
                float o1 = (acc[mf][nf][1] + bb1) * sigmoidf_(acc[mf][nf][3] + bb2);
                *(uint32_t*)(dst + nf * 8) = pk2(o0, o1);
            }
        }
    } else {
#pragma unroll
        for (int mf = 0; mf < 4; mf++) {
            const int ch = cbase + (warpM * 4 + mf) * 8 + g;
            const float bb1 = b1[ch], bb2 = b2[ch];
            __half* dv = g_v + ((size_t)b * C + ch) * N + n0 + ncol + 2 * tig;
            float sm = 0.f;
#pragma unroll
            for (int nf = 0; nf < 4; nf++) {
                float o0 = acc[mf][nf][0] + bb1;
                float o1 = acc[mf][nf][1] + bb1;
                *(uint32_t*)(dv + nf * 8) = pk2(o0, o1);
                sm += sigmoidf_(acc[mf][nf][2] + bb2) + sigmoidf_(acc[mf][nf][3] + bb2);
            }
            sm += __shfl_xor_sync(0xffffffffu, sm, 1);
            sm += __shfl_xor_sync(0xffffffffu, sm, 2);
            if (tig == 0) red[(warpM * 4 + mf) * 8 + g][warpN] = sm;
        }
        __syncthreads();
        if (tid < 64)
            g_fsum[((size_t)b * NTILES + blockIdx.y) * C + cbase + tid] =
                red[tid][0] + red[tid][1] + red[tid][2] + red[tid][3];
    }
}

// ---------------------------------------------------------------------------
// Kernel 2: knowledge partials (NT GEMM, fp16 raw loads), K=1024 per block.
// ---------------------------------------------------------------------------
__global__ void __launch_bounds__(256, 2)
know_h()
{
    __shared__ uint32_t As[16][LDS_];
    __shared__ uint32_t Bs[16][LDS_];

    const int s = blockIdx.x, b = blockIdx.y;
    const int tid = threadIdx.x, lane = tid & 31, warp = tid >> 5;
    const int g = lane >> 2, tig = lane & 3;
    const int warpM = warp & 1, warpN = warp >> 1;
    const int mrow = warpM * 64, ncol = warpN * 32;

    const int am = tid >> 1;
    const __half* arow = g_kg + ((size_t)b * C + am) * N + (size_t)s * CHUNK;
    const __half* brow = g_v  + ((size_t)b * C + am) * N + (size_t)s * CHUNK;
    const int koff = (tid & 1) << 4;

    float acc[4][4][4] = {};
#pragma unroll 1
    for (int ss = 0; ss < CHUNK / 32; ss++) {
        stsT_raw_h(As, arow + ss * 32 + koff, tid);
        stsT_raw_h(Bs, brow + ss * 32 + koff, tid);
        __syncthreads();
        compute_slab_h(As, Bs, acc, mrow, ncol, g, tig);
        __syncthreads();
    }

    float* dst = g_part + ((size_t)b * SPLITK + s) * C * C;
#pragma unroll
    for (int mf = 0; mf < 4; mf++) {
        const int row = mrow + mf * 16 + g;
#pragma unroll
        for (int nf = 0; nf < 4; nf++) {
            const int col = ncol + nf * 8 + 2 * tig;
            *(float2*)(dst + (size_t)row * C + col)       = make_float2(acc[mf][nf][0], acc[mf][nf][1]);
            *(float2*)(dst + (size_t)(row + 8) * C + col) = make_float2(acc[mf][nf][2], acc[mf][nf][3]);
        }
    }
}

// ---------------------------------------------------------------------------
// Kernel 3: fused scalar tail (fp32). fs = mean(sig(forget)); M -> d_out tail;
// E = Wp*M^T; F = E*Wq; fb = E*bq + bp.
// ---------------------------------------------------------------------------
__global__ void __launch_bounds__(256)
tail_h(const float* __restrict__ prev, const float* __restrict__ Wp,
       const float* __restrict__ Wq, const float* __restrict__ bq,
       const float* __restrict__ bp, float* __restrict__ dout)
{
    __shared__ float fs[128];
    const int b = blockIdx.x, tid = threadIdx.x;

    if (tid < 128) {
        const float* p = g_fsum + (size_t)b * NTILES * C + tid;
        float sm = 0.f;
        for (int i = 0; i < NTILES; i++) sm += p[(size_t)i * C];
        fs[tid] = sm * (1.0f / (float)N);
    }
    __syncthreads();

    float* M = dout + OUT_ELEMS + (size_t)b * C * C;
    for (int e = tid; e < C * C; e += 256) {
        float a = fs[e >> 7] * prev[(size_t)b * C * C + e];
#pragma unroll
        for (int s2 = 0; s2 < SPLITK; s2++)
            a += g_part[((size_t)b * SPLITK + s2) * C * C + e];
        M[e] = a;
    }
    __syncthreads();

    // E[o][c] = dot(Wp row o, M row c)
    for (int e = tid; e < C * C; e += 256) {
        const int o = e >> 7, c = e & 127;
        const float4* wr = (const float4*)(Wp + (size_t)o * C);
        const float4* mr = (const float4*)(M + (size_t)c * C);
        float s = 0.f;
#pragma unroll 8
        for (int k = 0; k < 32; k++) {
            float4 a = wr[k], m = mr[k];
            s += a.x * m.x + a.y * m.y + a.z * m.z + a.w * m.w;
        }
        g_E[(size_t)b * C * C + e] = s;
    }
    __syncthreads();

    // F[o][j] = sum_k E[o][k] * Wq[k][j] ; fb[o] = dot(E row o, bq) + bp[o]
    const float* E = g_E + (size_t)b * C * C;
    for (int e = tid; e < C * C; e += 256) {
        const int o = e >> 7, j = e & 127;
        const float* er = E + (size_t)o * C;
        float s = 0.f;
#pragma unroll 8
        for (int k = 0; k < C; k++) s = fmaf(er[k], Wq[(size_t)k * C + j], s);
        g_F[(size_t)b * C * C + e] = s;
    }
    if (tid < 128) {
        const float* er = E + (size_t)tid * C;
        float s = bp[tid];
        for (int k = 0; k < C; k++) s = fmaf(er[k], bq[k], s);
        g_fb[(size_t)b * C + tid] = s;
    }
}

// ---------------------------------------------------------------------------
// Kernel 4: out = F*x + fb + x (fp16 tensor cores, fp32 residual epilogue).
// ---------------------------------------------------------------------------
__global__ void __launch_bounds__(256, 2)
out_h(const float* __restrict__ x, float* __restrict__ dout)
{
    __shared__ uint32_t As[16][LDS_];
    __shared__ uint32_t Bs[16][LDS_];

    const int n0 = blockIdx.x << 7;
    const int b  = blockIdx.y;
    const float* xb = x + (size_t)b * C * N;

    const int tid = threadIdx.x, lane = tid & 31, warp = tid >> 5;
    const int g = lane >> 2, tig = lane & 3;
    const int warpM = warp & 1, warpN = warp >> 1;
    const int mrow = warpM * 64, ncol = warpN * 32;

    const int am = tid >> 1;
    const float* myArow = g_F + (size_t)b * C * C + (size_t)am * C;

    float acc[4][4][4] = {};
#pragma unroll 1
    for (int kk = 0; kk < C; kk += 32) {
        stsT_h(As, myArow + kk + ((tid & 1) << 4), tid);
        stsD_h(Bs, xb + (size_t)kk * N + n0, N, tid);
        __syncthreads();
        compute_slab_h(As, Bs, acc, mrow, ncol, g, tig);
        __syncthreads();
    }

#pragma unroll
    for (int mf = 0; mf < 4; mf++) {
        const int o = mrow + mf * 16 + g;
        const float fb0 = g_fb[(size_t)b * C + o];
        const float fb1 = g_fb[(size_t)b * C + o + 8];
#pragma unroll
        for (int nf = 0; nf < 4; nf++) {
            const int col = n0 + ncol + nf * 8 + 2 * tig;
            float2 r0 = *(const float2*)(xb + (size_t)o * N + col);
            float2 r1 = *(const float2*)(xb + (size_t)(o + 8) * N + col);
            *(float2*)(dout + ((size_t)b * C + o) * N + col) =
                make_float2(acc[mf][nf][0] + fb0 + r0.x, acc[mf][nf][1] + fb0 + r0.y);
            *(float2*)(dout + ((size_t)b * C + o + 8) * N + col) =
                make_float2(acc[mf][nf][2] + fb1 + r1.x, acc[mf][nf][3] + fb1 + r1.y);
        }
    }
}

// ---------------------------------------------------------------------------
extern "C" void kernel_launch(void* const* d_in, const int* in_sizes, int n_in,
                              void* d_out, int out_size)
{
    const float* x    = (const float*)d_in[0];
    const float* prev = (const float*)d_in[1];
    const float* Wq   = (const float*)d_in[2];
    const float* bq   = (const float*)d_in[3];
    const float* Wk   = (const float*)d_in[4];
    const float* bk   = (const float*)d_in[5];
    const float* Wv   = (const float*)d_in[6];
    const float* bv   = (const float*)d_in[7];
    const float* Wg   = (const float*)d_in[8];
    const float* bg   = (const float*)d_in[9];
    const float* Wp   = (const float*)d_in[10];
    const float* bp   = (const float*)d_in[11];
    float* out = (float*)d_out;

    proj_h<<<dim3(4, NTILES, BATCH), 256>>>(x, Wk, bk, Wv, bv, Wg, bg);
    know_h<<<dim3(SPLITK, BATCH), 256>>>();
    tail_h<<<BATCH, 256>>>(prev, Wp, Wq, bq, bp, out);
    out_h<<<dim3(NTILES, BATCH), 256>>>(x, out);
}

// round 15
// speedup vs baseline: 1.4344x; 1.4344x over previous
#include <cuda_runtime.h>
#include <cuda_fp16.h>
#include <stdint.h>
#include <math.h>

static constexpr int BATCH  = 16;
static constexpr int C      = 128;
static constexpr int N      = 16384;
static constexpr int SPLITK = 16;
static constexpr int CHUNK  = N / SPLITK;    // 1024
static constexpr int NTILES = N / 128;       // 128
static constexpr size_t OUT_ELEMS = (size_t)BATCH * C * N;
static constexpr int LDS_ = 136;             // padded smem stride (words)

// ---------------- scratch (static device globals; no allocations) ----------
__device__ float g_kg  [(size_t)BATCH * C * N];          // tf32 bit patterns
__device__ float g_v   [(size_t)BATCH * C * N];          // tf32 bit patterns
__device__ float g_part[(size_t)BATCH * SPLITK * C * C];
__device__ float g_fsum[(size_t)BATCH * C * NTILES];     // [b][c][tile]
__device__ float g_E   [(size_t)BATCH * C * C];
__device__ float g_F   [(size_t)BATCH * C * C];
__device__ float g_fb  [(size_t)BATCH * C];

__device__ __forceinline__ float sigmoidf_(float v) { return 1.0f / (1.0f + __expf(-v)); }

__device__ __forceinline__ uint32_t f2tf(float f) {
    uint32_t u; asm("cvt.rna.tf32.f32 %0, %1;" : "=r"(u) : "f"(f)); return u;
}
__device__ __forceinline__ uint32_t pk2(float a, float b) {
    __half2 h = __floats2half2_rn(a, b);
    return *(uint32_t*)&h;
}

__device__ __forceinline__ void mma_tf32(float c[4],
    uint32_t a0, uint32_t a1, uint32_t a2, uint32_t a3, uint32_t b0, uint32_t b1)
{
    asm volatile(
        "mma.sync.aligned.m16n8k8.row.col.f32.tf32.tf32.f32 "
        "{%0,%1,%2,%3}, {%4,%5,%6,%7}, {%8,%9}, {%0,%1,%2,%3};\n"
        : "+f"(c[0]), "+f"(c[1]), "+f"(c[2]), "+f"(c[3])
        : "r"(a0), "r"(a1), "r"(a2), "r"(a3), "r"(b0), "r"(b1));
}
__device__ __forceinline__ void mma_f16(float c[4],
    uint32_t a0, uint32_t a1, uint32_t a2, uint32_t a3, uint32_t b0, uint32_t b1)
{
    asm volatile(
        "mma.sync.aligned.m16n8k16.row.col.f32.f16.f16.f32 "
        "{%0,%1,%2,%3}, {%4,%5,%6,%7}, {%8,%9}, {%0,%1,%2,%3};\n"
        : "+f"(c[0]), "+f"(c[1]), "+f"(c[2]), "+f"(c[3])
        : "r"(a0), "r"(a1), "r"(a2), "r"(a3), "r"(b0), "r"(b1));
}

// ================= R7 tf32 machinery (measured-best, verbatim) ==============
// Transpose loader: S[k][m] = myrow[kbase + k], thread owns m = tid>>1, koff = (tid&1)*8.
__device__ __forceinline__ void load_transpose(uint32_t (*S)[LDS_], const float* myrow,
                                               int kbase, int tid)
{
    const int m = tid >> 1, koff = (tid & 1) << 3;
    const float* p = myrow + kbase + koff;
    float4 u = *(const float4*)p;
    float4 v = *(const float4*)(p + 4);
    S[koff + 0][m] = f2tf(u.x); S[koff + 1][m] = f2tf(u.y);
    S[koff + 2][m] = f2tf(u.z); S[koff + 3][m] = f2tf(u.w);
    S[koff + 4][m] = f2tf(v.x); S[koff + 5][m] = f2tf(v.y);
    S[koff + 6][m] = f2tf(v.z); S[koff + 7][m] = f2tf(v.w);
}
// Direct loader: S[k][n] = src[(kbase+k)*ld + n0 + n]
__device__ __forceinline__ void load_direct(uint32_t (*S)[LDS_], const float* src,
                                            size_t ld, int n0, int kbase, int tid)
{
    const int kb = tid >> 4, nb = (tid & 15) << 3;
    const float* p = src + (size_t)(kbase + kb) * ld + n0 + nb;
    float4 u = *(const float4*)p;
    float4 v = *(const float4*)(p + 4);
    *(uint4*)&S[kb][nb]     = make_uint4(f2tf(u.x), f2tf(u.y), f2tf(u.z), f2tf(u.w));
    *(uint4*)&S[kb][nb + 4] = make_uint4(f2tf(v.x), f2tf(v.y), f2tf(v.z), f2tf(v.w));
}

// One 16-deep K-slab. Warp tile 64x32 (4 mfrag x 4 nfrag).
__device__ __forceinline__ void compute_slab(const uint32_t (*As)[LDS_], const uint32_t (*Bs)[LDS_],
                                             float acc[4][4][4], int mrow, int ncol, int g, int tig)
{
#pragma unroll
    for (int ks = 0; ks < 2; ks++) {
        uint32_t a[4][4], b[4][2];
#pragma unroll
        for (int mf = 0; mf < 4; mf++) {
            const int m = mrow + mf * 16 + g;
            a[mf][0] = As[ks * 8 + tig][m];
            a[mf][1] = As[ks * 8 + tig][m + 8];
            a[mf][2] = As[ks * 8 + tig + 4][m];
            a[mf][3] = As[ks * 8 + tig + 4][m + 8];
        }
#pragma unroll
        for (int nf = 0; nf < 4; nf++) {
            const int n = ncol + nf * 8 + g;
            b[nf][0] = Bs[ks * 8 + tig][n];
            b[nf][1] = Bs[ks * 8 + tig + 4][n];
        }
#pragma unroll
        for (int mf = 0; mf < 4; mf++)
#pragma unroll
            for (int nf = 0; nf < 4; nf++)
                mma_tf32(acc[mf][nf], a[mf][0], a[mf][1], a[mf][2], a[mf][3],
                         b[nf][0], b[nf][1]);
    }
}

// ---------------------------------------------------------------------------
// Kernel 1: fused projections (R7 verbatim).
// ---------------------------------------------------------------------------
__global__ void __launch_bounds__(256, 2)
proj_tc(const float* __restrict__ x,
        const float* __restrict__ Wk, const float* __restrict__ bk,
        const float* __restrict__ Wv, const float* __restrict__ bv,
        const float* __restrict__ Wg, const float* __restrict__ bg)
{
    __shared__ uint32_t As[16][LDS_];
    __shared__ uint32_t Bs[16][LDS_];
    __shared__ float red[64][4];

    const int idx   = blockIdx.x;
    const int type  = idx >> 1;
    const int cbase = (idx & 1) * 64;
    const int n0    = blockIdx.y << 7;
    const int b     = blockIdx.z;

    const float *W1, *W2, *b1, *b2;
    if (type == 0) { W1 = Wk; b1 = bk; W2 = Wg + C * C; b2 = bg + C; }
    else           { W1 = Wv; b1 = bv; W2 = Wg;         b2 = bg;     }

    const int tid = threadIdx.x, lane = tid & 31, warp = tid >> 5;
    const int g = lane >> 2, tig = lane & 3;
    const int warpM = warp & 1, warpN = warp >> 1;
    const int mrow = warpM * 64, ncol = warpN * 32;

    const int am = tid >> 1;
    const int agrp = am >> 4, awi = am & 15;
    const int ach = cbase + agrp * 8 + (awi & 7);
    const float* myArow = ((awi < 8) ? W1 : W2) + (size_t)ach * C;
    const float* xb = x + (size_t)b * C * N;

    float acc[4][4][4] = {};
#pragma unroll 1
    for (int kk = 0; kk < C; kk += 16) {
        load_transpose(As, myArow, kk, tid);
        load_direct(Bs, xb, N, n0, kk, tid);
        __syncthreads();
        compute_slab(As, Bs, acc, mrow, ncol, g, tig);
        __syncthreads();
    }

    if (type == 0) {
#pragma unroll
        for (int mf = 0; mf < 4; mf++) {
            const int ch = cbase + (warpM * 4 + mf) * 8 + g;
            const float bb1 = b1[ch], bb2 = b2[ch];
            float* dst = g_kg + ((size_t)b * C + ch) * N + n0 + ncol + 2 * tig;
#pragma unroll
            for (int nf = 0; nf < 4; nf++) {
                float o0 = (acc[mf][nf][0] + bb1) * sigmoidf_(acc[mf][nf][2] + bb2);
                float o1 = (acc[mf][nf][1] + bb1) * sigmoidf_(acc[mf][nf][3] + bb2);
                *(float2*)(dst + nf * 8) = make_float2(o0, o1);
            }
        }
    } else {
#pragma unroll
        for (int mf = 0; mf < 4; mf++) {
            const int ch = cbase + (warpM * 4 + mf) * 8 + g;
            const float bb1 = b1[ch], bb2 = b2[ch];
            float* dv = g_v + ((size_t)b * C + ch) * N + n0 + ncol + 2 * tig;
            float s = 0.f;
#pragma unroll
            for (int nf = 0; nf < 4; nf++) {
                *(float2*)(dv + nf * 8) = make_float2(acc[mf][nf][0] + bb1,
                                                      acc[mf][nf][1] + bb1);
                s += sigmoidf_(acc[mf][nf][2] + bb2) + sigmoidf_(acc[mf][nf][3] + bb2);
            }
            s += __shfl_xor_sync(0xffffffffu, s, 1);
            s += __shfl_xor_sync(0xffffffffu, s, 2);
            if (tig == 0) red[warpM * 32 + mf * 8 + g][warpN] = s;
        }
        __syncthreads();
        if (tid < 64) {
            float s = red[tid][0] + red[tid][1] + red[tid][2] + red[tid][3];
            g_fsum[((size_t)b * C + cbase + tid) * NTILES + blockIdx.y] = s;
        }
    }
}

// ---------------------------------------------------------------------------
// Kernel 2: knowledge partials (R7 verbatim).
// ---------------------------------------------------------------------------
__global__ void __launch_bounds__(256, 2)
know_tc()
{
    __shared__ uint32_t As[16][LDS_];
    __shared__ uint32_t Bs[16][LDS_];

    const int s = blockIdx.x, b = blockIdx.y;
    const int tid = threadIdx.x, lane = tid & 31, warp = tid >> 5;
    const int g = lane >> 2, tig = lane & 3;
    const int warpM = warp & 1, warpN = warp >> 1;
    const int mrow = warpM * 64, ncol = warpN * 32;

    const int am = tid >> 1;
    const float* arow = g_kg + ((size_t)b * C + am) * N + (size_t)s * CHUNK;
    const float* brow = g_v  + ((size_t)b * C + am) * N + (size_t)s * CHUNK;

    float acc[4][4][4] = {};
#pragma unroll 1
    for (int kk = 0; kk < CHUNK; kk += 16) {
        load_transpose(As, arow, kk, tid);
        load_transpose(Bs, brow, kk, tid);
        __syncthreads();
        compute_slab(As, Bs, acc, mrow, ncol, g, tig);
        __syncthreads();
    }

    float* dst = g_part + ((size_t)b * SPLITK + s) * C * C;
#pragma unroll
    for (int mf = 0; mf < 4; mf++) {
        const int row = mrow + mf * 16 + g;
#pragma unroll
        for (int nf = 0; nf < 4; nf++) {
            const int col = ncol + nf * 8 + 2 * tig;
            *(float2*)(dst + (size_t)row * C + col)       = make_float2(acc[mf][nf][0], acc[mf][nf][1]);
            *(float2*)(dst + (size_t)(row + 8) * C + col) = make_float2(acc[mf][nf][2], acc[mf][nf][3]);
        }
    }
}

// ---------------------------------------------------------------------------
// Kernel 3: new_memory (R7 verbatim).
// ---------------------------------------------------------------------------
__global__ void mem_kernel(const float* __restrict__ prev, float* __restrict__ dout)
{
    const int b = blockIdx.x;
    const int tid = threadIdx.x;
    __shared__ float fs[128];
    if (tid < 128) {
        const float* p = g_fsum + ((size_t)b * C + tid) * NTILES;
        float s = 0.f;
        for (int i = 0; i < NTILES; i++) s += p[i];
        fs[tid] = s * (1.0f / (float)N);
    }
    __syncthreads();
    for (int e = tid; e < C * C; e += 256) {
        const int c = e >> 7;
        float a = fs[c] * prev[(size_t)b * C * C + e];
#pragma unroll
        for (int s2 = 0; s2 < SPLITK; s2++)
            a += g_part[((size_t)b * SPLITK + s2) * C * C + e];
        dout[OUT_ELEMS + (size_t)b * C * C + e] = a;
    }
}

// ---------------------------------------------------------------------------
// Kernel 4: E = Wp * M^T (R7 verbatim).
// ---------------------------------------------------------------------------
__global__ void __launch_bounds__(256, 2)
e_tc(const float* __restrict__ Wp, const float* __restrict__ dout)
{
    __shared__ uint32_t As[16][LDS_];
    __shared__ uint32_t Bs[16][LDS_];
    const int b = blockIdx.x;
    const float* M = dout + OUT_ELEMS + (size_t)b * C * C;

    const int tid = threadIdx.x, lane = tid & 31, warp = tid >> 5;
    const int g = lane >> 2, tig = lane & 3;
    const int warpM = warp & 1, warpN = warp >> 1;
    const int mrow = warpM * 64, ncol = warpN * 32;

    const int am = tid >> 1;
    const float* arow = Wp + (size_t)am * C;
    const float* brow = M  + (size_t)am * C;

    float acc[4][4][4] = {};
#pragma unroll 1
    for (int kk = 0; kk < C; kk += 16) {
        load_transpose(As, arow, kk, tid);
        load_transpose(Bs, brow, kk, tid);
        __syncthreads();
        compute_slab(As, Bs, acc, mrow, ncol, g, tig);
        __syncthreads();
    }

    float* dst = g_E + (size_t)b * C * C;
#pragma unroll
    for (int mf = 0; mf < 4; mf++) {
        const int row = mrow + mf * 16 + g;
#pragma unroll
        for (int nf = 0; nf < 4; nf++) {
            const int col = ncol + nf * 8 + 2 * tig;
            *(float2*)(dst + (size_t)row * C + col)       = make_float2(acc[mf][nf][0], acc[mf][nf][1]);
            *(float2*)(dst + (size_t)(row + 8) * C + col) = make_float2(acc[mf][nf][2], acc[mf][nf][3]);
        }
    }
}

// ---------------------------------------------------------------------------
// Kernel 5: F = E * Wq ; fb = E*bq + bp (R7 verbatim).
// ---------------------------------------------------------------------------
__global__ void __launch_bounds__(256, 2)
f_tc(const float* __restrict__ Wq, const float* __restrict__ bq,
     const float* __restrict__ bp)
{
    __shared__ uint32_t As[16][LDS_];
    __shared__ uint32_t Bs[16][LDS_];
    const int b = blockIdx.x;
    const float* E = g_E + (size_t)b * C * C;

    const int tid = threadIdx.x, lane = tid & 31, warp = tid >> 5;
    const int g = lane >> 2, tig = lane & 3;
    const int warpM = warp & 1, warpN = warp >> 1;
    const int mrow = warpM * 64, ncol = warpN * 32;

    const int am = tid >> 1;
    const float* arow = E + (size_t)am * C;

    float acc[4][4][4] = {};
#pragma unroll 1
    for (int kk = 0; kk < C; kk += 16) {
        load_transpose(As, arow, kk, tid);
        load_direct(Bs, Wq, C, 0, kk, tid);
        __syncthreads();
        compute_slab(As, Bs, acc, mrow, ncol, g, tig);
        __syncthreads();
    }

    float* dst = g_F + (size_t)b * C * C;
#pragma unroll
    for (int mf = 0; mf < 4; mf++) {
        const int row = mrow + mf * 16 + g;
#pragma unroll
        for (int nf = 0; nf < 4; nf++) {
            const int col = ncol + nf * 8 + 2 * tig;
            *(float2*)(dst + (size_t)row * C + col)       = make_float2(acc[mf][nf][0], acc[mf][nf][1]);
            *(float2*)(dst + (size_t)(row + 8) * C + col) = make_float2(acc[mf][nf][2], acc[mf][nf][3]);
        }
    }
    __syncthreads();
    if (tid < 128) {
        float s = bp[tid];
        const float* er = E + (size_t)tid * C;
        for (int c = 0; c < C; c++) s = fmaf(er[c], bq[c], s);
        g_fb[(size_t)b * C + tid] = s;
    }
}

// ================= R14 fp16 machinery (measured: out 99 µs) =================
__device__ __forceinline__ void stsT_h(uint32_t (*S)[LDS_], const float* p, int tid) {
    const int m = tid >> 1, ko = (tid & 1) << 3;
    float4 u0 = *(const float4*)(p);
    float4 u1 = *(const float4*)(p + 4);
    float4 u2 = *(const float4*)(p + 8);
    float4 u3 = *(const float4*)(p + 12);
    S[ko + 0][m] = pk2(u0.x, u0.y); S[ko + 1][m] = pk2(u0.z, u0.w);
    S[ko + 2][m] = pk2(u1.x, u1.y); S[ko + 3][m] = pk2(u1.z, u1.w);
    S[ko + 4][m] = pk2(u2.x, u2.y); S[ko + 5][m] = pk2(u2.z, u2.w);
    S[ko + 6][m] = pk2(u3.x, u3.y); S[ko + 7][m] = pk2(u3.z, u3.w);
}
__device__ __forceinline__ void stsD_h(uint32_t (*S)[LDS_], const float* src, size_t ld, int tid) {
    const int kb = tid >> 4, nb = (tid & 15) << 3;
    const float* r0 = src + (size_t)(2 * kb) * ld + nb;
    const float* r1 = r0 + ld;
    float4 a0 = *(const float4*)r0, a1 = *(const float4*)(r0 + 4);
    float4 b0 = *(const float4*)r1, b1 = *(const float4*)(r1 + 4);
    *(uint4*)&S[kb][nb]     = make_uint4(pk2(a0.x, b0.x), pk2(a0.y, b0.y),
                                         pk2(a0.z, b0.z), pk2(a0.w, b0.w));
    *(uint4*)&S[kb][nb + 4] = make_uint4(pk2(a1.x, b1.x), pk2(a1.y, b1.y),
                                         pk2(a1.z, b1.z), pk2(a1.w, b1.w));
}
__device__ __forceinline__ void compute_slab_h(const uint32_t (*As)[LDS_], const uint32_t (*Bs)[LDS_],
                                               float acc[4][4][4], int mrow, int ncol, int g, int tig)
{
#pragma unroll
    for (int ks = 0; ks < 2; ks++) {
        uint32_t a[4][4], b[4][2];
#pragma unroll
        for (int mf = 0; mf < 4; mf++) {
            const int m = mrow + mf * 16 + g;
            a[mf][0] = As[ks * 8 + tig][m];     a[mf][1] = As[ks * 8 + tig][m + 8];
            a[mf][2] = As[ks * 8 + tig + 4][m]; a[mf][3] = As[ks * 8 + tig + 4][m + 8];
        }
#pragma unroll
        for (int nf = 0; nf < 4; nf++) {
            const int n = ncol + nf * 8 + g;
            b[nf][0] = Bs[ks * 8 + tig][n]; b[nf][1] = Bs[ks * 8 + tig + 4][n];
        }
#pragma unroll
        for (int mf = 0; mf < 4; mf++)
#pragma unroll
            for (int nf = 0; nf < 4; nf++)
                mma_f16(acc[mf][nf], a[mf][0], a[mf][1], a[mf][2], a[mf][3],
                        b[nf][0], b[nf][1]);
    }
}

// ---------------------------------------------------------------------------
// Kernel 6: out = F*x + fb + x (R14 fp16 verbatim — measured 99 µs).
// ---------------------------------------------------------------------------
__global__ void __launch_bounds__(256, 2)
out_h(const float* __restrict__ x, float* __restrict__ dout)
{
    __shared__ uint32_t As[16][LDS_];
    __shared__ uint32_t Bs[16][LDS_];

    const int n0 = blockIdx.x << 7;
    const int b  = blockIdx.y;
    const float* xb = x + (size_t)b * C * N;

    const int tid = threadIdx.x, lane = tid & 31, warp = tid >> 5;
    const int g = lane >> 2, tig = lane & 3;
    const int warpM = warp & 1, warpN = warp >> 1;
    const int mrow = warpM * 64, ncol = warpN * 32;

    const int am = tid >> 1;
    const float* myArow = g_F + (size_t)b * C * C + (size_t)am * C;

    float acc[4][4][4] = {};
#pragma unroll 1
    for (int kk = 0; kk < C; kk += 32) {
        stsT_h(As, myArow + kk + ((tid & 1) << 4), tid);
        stsD_h(Bs, xb + (size_t)kk * N + n0, N, tid);
        __syncthreads();
        compute_slab_h(As, Bs, acc, mrow, ncol, g, tig);
        __syncthreads();
    }

#pragma unroll
    for (int mf = 0; mf < 4; mf++) {
        const int o = mrow + mf * 16 + g;
        const float fb0 = g_fb[(size_t)b * C + o];
        const float fb1 = g_fb[(size_t)b * C + o + 8];
#pragma unroll
        for (int nf = 0; nf < 4; nf++) {
            const int col = n0 + ncol + nf * 8 + 2 * tig;
            float2 r0 = *(const float2*)(xb + (size_t)o * N + col);
            float2 r1 = *(const float2*)(xb + (size_t)(o + 8) * N + col);
            *(float2*)(dout + ((size_t)b * C + o) * N + col) =
                make_float2(acc[mf][nf][0] + fb0 + r0.x, acc[mf][nf][1] + fb0 + r0.y);
            *(float2*)(dout + ((size_t)b * C + o + 8) * N + col) =
                make_float2(acc[mf][nf][2] + fb1 + r1.x, acc[mf][nf][3] + fb1 + r1.y);
        }
    }
}

// ---------------------------------------------------------------------------
extern "C" void kernel_launch(void* const* d_in, const int* in_sizes, int n_in,
                              void* d_out, int out_size)
{
    const float* x    = (const float*)d_in[0];
    const float* prev = (const float*)d_in[1];
    const float* Wq   = (const float*)d_in[2];
    const float* bq   = (const float*)d_in[3];
    const float* Wk   = (const float*)d_in[4];
    const float* bk   = (const float*)d_in[5];
    const float* Wv   = (const float*)d_in[6];
    const float* bv   = (const float*)d_in[7];
    const float* Wg   = (const float*)d_in[8];
    const float* bg   = (const float*)d_in[9];
    const float* Wp   = (const float*)d_in[10];
    const float* bp   = (const float*)d_in[11];
    float* out = (float*)d_out;

    proj_tc<<<dim3(4, NTILES, BATCH), 256>>>(x, Wk, bk, Wv, bv, Wg, bg);
    know_tc<<<dim3(SPLITK, BATCH), 256>>>();
    mem_kernel<<<BATCH, 256>>>(prev, out);
    e_tc<<<BATCH, 256>>>(Wp, out);
    f_tc<<<BATCH, 256>>>(Wq, bq, bp);
    out_h<<<dim3(NTILES, BATCH), 256>>>(x, out);
}

// round 16
// speedup vs baseline: 1.5468x; 1.0784x over previous
#include <cuda_runtime.h>
#include <cuda_fp16.h>
#include <stdint.h>
#include <math.h>

static constexpr int BATCH  = 16;
static constexpr int C      = 128;
static constexpr int N      = 16384;
static constexpr int SPLITK = 16;
static constexpr int CHUNK  = N / SPLITK;    // 1024
static constexpr int NTILES = N / 128;       // 128
static constexpr size_t OUT_ELEMS = (size_t)BATCH * C * N;
static constexpr int LDS_ = 136;             // padded smem stride (words)

// ---------------- scratch (static device globals; no allocations) ----------
__device__ __half g_kg [(size_t)BATCH * C * N];          // fp16
__device__ __half g_v  [(size_t)BATCH * C * N];          // fp16
__device__ float g_part[(size_t)BATCH * SPLITK * C * C];
__device__ float g_fsum[(size_t)BATCH * C * NTILES];     // [b][c][tile]
__device__ float g_E   [(size_t)BATCH * C * C];
__device__ float g_F   [(size_t)BATCH * C * C];
__device__ float g_fb  [(size_t)BATCH * C];

__device__ __forceinline__ float sigmoidf_(float v) { return 1.0f / (1.0f + __expf(-v)); }

__device__ __forceinline__ uint32_t f2tf(float f) {
    uint32_t u; asm("cvt.rna.tf32.f32 %0, %1;" : "=r"(u) : "f"(f)); return u;
}
__device__ __forceinline__ uint32_t pk2(float a, float b) {
    __half2 h = __floats2half2_rn(a, b);
    return *(uint32_t*)&h;
}

__device__ __forceinline__ void mma_tf32(float c[4],
    uint32_t a0, uint32_t a1, uint32_t a2, uint32_t a3, uint32_t b0, uint32_t b1)
{
    asm volatile(
        "mma.sync.aligned.m16n8k8.row.col.f32.tf32.tf32.f32 "
        "{%0,%1,%2,%3}, {%4,%5,%6,%7}, {%8,%9}, {%0,%1,%2,%3};\n"
        : "+f"(c[0]), "+f"(c[1]), "+f"(c[2]), "+f"(c[3])
        : "r"(a0), "r"(a1), "r"(a2), "r"(a3), "r"(b0), "r"(b1));
}
__device__ __forceinline__ void mma_f16(float c[4],
    uint32_t a0, uint32_t a1, uint32_t a2, uint32_t a3, uint32_t b0, uint32_t b1)
{
    asm volatile(
        "mma.sync.aligned.m16n8k16.row.col.f32.f16.f16.f32 "
        "{%0,%1,%2,%3}, {%4,%5,%6,%7}, {%8,%9}, {%0,%1,%2,%3};\n"
        : "+f"(c[0]), "+f"(c[1]), "+f"(c[2]), "+f"(c[3])
        : "r"(a0), "r"(a1), "r"(a2), "r"(a3), "r"(b0), "r"(b1));
}

// ================= tf32 machinery (R7 measured-best, verbatim) ==============
__device__ __forceinline__ void load_transpose(uint32_t (*S)[LDS_], const float* myrow,
                                               int kbase, int tid)
{
    const int m = tid >> 1, koff = (tid & 1) << 3;
    const float* p = myrow + kbase + koff;
    float4 u = *(const float4*)p;
    float4 v = *(const float4*)(p + 4);
    S[koff + 0][m] = f2tf(u.x); S[koff + 1][m] = f2tf(u.y);
    S[koff + 2][m] = f2tf(u.z); S[koff + 3][m] = f2tf(u.w);
    S[koff + 4][m] = f2tf(v.x); S[koff + 5][m] = f2tf(v.y);
    S[koff + 6][m] = f2tf(v.z); S[koff + 7][m] = f2tf(v.w);
}
__device__ __forceinline__ void load_direct(uint32_t (*S)[LDS_], const float* src,
                                            size_t ld, int n0, int kbase, int tid)
{
    const int kb = tid >> 4, nb = (tid & 15) << 3;
    const float* p = src + (size_t)(kbase + kb) * ld + n0 + nb;
    float4 u = *(const float4*)p;
    float4 v = *(const float4*)(p + 4);
    *(uint4*)&S[kb][nb]     = make_uint4(f2tf(u.x), f2tf(u.y), f2tf(u.z), f2tf(u.w));
    *(uint4*)&S[kb][nb + 4] = make_uint4(f2tf(v.x), f2tf(v.y), f2tf(v.z), f2tf(v.w));
}
__device__ __forceinline__ void compute_slab(const uint32_t (*As)[LDS_], const uint32_t (*Bs)[LDS_],
                                             float acc[4][4][4], int mrow, int ncol, int g, int tig)
{
#pragma unroll
    for (int ks = 0; ks < 2; ks++) {
        uint32_t a[4][4], b[4][2];
#pragma unroll
        for (int mf = 0; mf < 4; mf++) {
            const int m = mrow + mf * 16 + g;
            a[mf][0] = As[ks * 8 + tig][m];
            a[mf][1] = As[ks * 8 + tig][m + 8];
            a[mf][2] = As[ks * 8 + tig + 4][m];
            a[mf][3] = As[ks * 8 + tig + 4][m + 8];
        }
#pragma unroll
        for (int nf = 0; nf < 4; nf++) {
            const int n = ncol + nf * 8 + g;
            b[nf][0] = Bs[ks * 8 + tig][n];
            b[nf][1] = Bs[ks * 8 + tig + 4][n];
        }
#pragma unroll
        for (int mf = 0; mf < 4; mf++)
#pragma unroll
            for (int nf = 0; nf < 4; nf++)
                mma_tf32(acc[mf][nf], a[mf][0], a[mf][1], a[mf][2], a[mf][3],
                         b[nf][0], b[nf][1]);
    }
}

// ================= fp16 machinery (R14, out_h measured 99 µs) ===============
__device__ __forceinline__ void stsT_h(uint32_t (*S)[LDS_], const float* p, int tid) {
    const int m = tid >> 1, ko = (tid & 1) << 3;
    float4 u0 = *(const float4*)(p);
    float4 u1 = *(const float4*)(p + 4);
    float4 u2 = *(const float4*)(p + 8);
    float4 u3 = *(const float4*)(p + 12);
    S[ko + 0][m] = pk2(u0.x, u0.y); S[ko + 1][m] = pk2(u0.z, u0.w);
    S[ko + 2][m] = pk2(u1.x, u1.y); S[ko + 3][m] = pk2(u1.z, u1.w);
    S[ko + 4][m] = pk2(u2.x, u2.y); S[ko + 5][m] = pk2(u2.z, u2.w);
    S[ko + 6][m] = pk2(u3.x, u3.y); S[ko + 7][m] = pk2(u3.z, u3.w);
}
__device__ __forceinline__ void stsT_raw_h(uint32_t (*S)[LDS_], const __half* p, int tid) {
    const int m = tid >> 1, ko = (tid & 1) << 3;
    uint4 a = *(const uint4*)(p);
    uint4 b = *(const uint4*)(p + 8);
    S[ko + 0][m] = a.x; S[ko + 1][m] = a.y; S[ko + 2][m] = a.z; S[ko + 3][m] = a.w;
    S[ko + 4][m] = b.x; S[ko + 5][m] = b.y; S[ko + 6][m] = b.z; S[ko + 7][m] = b.w;
}
__device__ __forceinline__ void stsD_h(uint32_t (*S)[LDS_], const float* src, size_t ld, int tid) {
    const int kb = tid >> 4, nb = (tid & 15) << 3;
    const float* r0 = src + (size_t)(2 * kb) * ld + nb;
    const float* r1 = r0 + ld;
    float4 a0 = *(const float4*)r0, a1 = *(const float4*)(r0 + 4);
    float4 b0 = *(const float4*)r1, b1 = *(const float4*)(r1 + 4);
    *(uint4*)&S[kb][nb]     = make_uint4(pk2(a0.x, b0.x), pk2(a0.y, b0.y),
                                         pk2(a0.z, b0.z), pk2(a0.w, b0.w));
    *(uint4*)&S[kb][nb + 4] = make_uint4(pk2(a1.x, b1.x), pk2(a1.y, b1.y),
                                         pk2(a1.z, b1.z), pk2(a1.w, b1.w));
}
__device__ __forceinline__ void compute_slab_h(const uint32_t (*As)[LDS_], const uint32_t (*Bs)[LDS_],
                                               float acc[4][4][4], int mrow, int ncol, int g, int tig)
{
#pragma unroll
    for (int ks = 0; ks < 2; ks++) {
        uint32_t a[4][4], b[4][2];
#pragma unroll
        for (int mf = 0; mf < 4; mf++) {
            const int m = mrow + mf * 16 + g;
            a[mf][0] = As[ks * 8 + tig][m];     a[mf][1] = As[ks * 8 + tig][m + 8];
            a[mf][2] = As[ks * 8 + tig + 4][m]; a[mf][3] = As[ks * 8 + tig + 4][m + 8];
        }
#pragma unroll
        for (int nf = 0; nf < 4; nf++) {
            const int n = ncol + nf * 8 + g;
            b[nf][0] = Bs[ks * 8 + tig][n]; b[nf][1] = Bs[ks * 8 + tig + 4][n];
        }
#pragma unroll
        for (int mf = 0; mf < 4; mf++)
#pragma unroll
            for (int nf = 0; nf < 4; nf++)
                mma_f16(acc[mf][nf], a[mf][0], a[mf][1], a[mf][2], a[mf][3],
                        b[nf][0], b[nf][1]);
    }
}

// ---------------------------------------------------------------------------
// Kernel 1: fused projections — R7 tf32 compute, fp16 kg/v stores (this
// round's single variable, part 1).
// ---------------------------------------------------------------------------
__global__ void __launch_bounds__(256, 2)
proj_tc(const float* __restrict__ x,
        const float* __restrict__ Wk, const float* __restrict__ bk,
        const float* __restrict__ Wv, const float* __restrict__ bv,
        const float* __restrict__ Wg, const float* __restrict__ bg)
{
    __shared__ uint32_t As[16][LDS_];
    __shared__ uint32_t Bs[16][LDS_];
    __shared__ float red[64][4];

    const int idx   = blockIdx.x;
    const int type  = idx >> 1;
    const int cbase = (idx & 1) * 64;
    const int n0    = blockIdx.y << 7;
    const int b     = blockIdx.z;

    const float *W1, *W2, *b1, *b2;
    if (type == 0) { W1 = Wk; b1 = bk; W2 = Wg + C * C; b2 = bg + C; }
    else           { W1 = Wv; b1 = bv; W2 = Wg;         b2 = bg;     }

    const int tid = threadIdx.x, lane = tid & 31, warp = tid >> 5;
    const int g = lane >> 2, tig = lane & 3;
    const int warpM = warp & 1, warpN = warp >> 1;
    const int mrow = warpM * 64, ncol = warpN * 32;

    const int am = tid >> 1;
    const int agrp = am >> 4, awi = am & 15;
    const int ach = cbase + agrp * 8 + (awi & 7);
    const float* myArow = ((awi < 8) ? W1 : W2) + (size_t)ach * C;
    const float* xb = x + (size_t)b * C * N;

    float acc[4][4][4] = {};
#pragma unroll 1
    for (int kk = 0; kk < C; kk += 16) {
        load_transpose(As, myArow, kk, tid);
        load_direct(Bs, xb, N, n0, kk, tid);
        __syncthreads();
        compute_slab(As, Bs, acc, mrow, ncol, g, tig);
        __syncthreads();
    }

    if (type == 0) {
#pragma unroll
        for (int mf = 0; mf < 4; mf++) {
            const int ch = cbase + (warpM * 4 + mf) * 8 + g;
            const float bb1 = b1[ch], bb2 = b2[ch];
            __half* dst = g_kg + ((size_t)b * C + ch) * N + n0 + ncol + 2 * tig;
#pragma unroll
            for (int nf = 0; nf < 4; nf++) {
                float o0 = (acc[mf][nf][0] + bb1) * sigmoidf_(acc[mf][nf][2] + bb2);
                float o1 = (acc[mf][nf][1] + bb1) * sigmoidf_(acc[mf][nf][3] + bb2);
                *(uint32_t*)(dst + nf * 8) = pk2(o0, o1);
            }
        }
    } else {
#pragma unroll
        for (int mf = 0; mf < 4; mf++) {
            const int ch = cbase + (warpM * 4 + mf) * 8 + g;
            const float bb1 = b1[ch], bb2 = b2[ch];
            __half* dv = g_v + ((size_t)b * C + ch) * N + n0 + ncol + 2 * tig;
            float s = 0.f;
#pragma unroll
            for (int nf = 0; nf < 4; nf++) {
                *(uint32_t*)(dv + nf * 8) = pk2(acc[mf][nf][0] + bb1,
                                                acc[mf][nf][1] + bb1);
                s += sigmoidf_(acc[mf][nf][2] + bb2) + sigmoidf_(acc[mf][nf][3] + bb2);
            }
            s += __shfl_xor_sync(0xffffffffu, s, 1);
            s += __shfl_xor_sync(0xffffffffu, s, 2);
            if (tig == 0) red[warpM * 32 + mf * 8 + g][warpN] = s;
        }
        __syncthreads();
        if (tid < 64) {
            float s = red[tid][0] + red[tid][1] + red[tid][2] + red[tid][3];
            g_fsum[((size_t)b * C + cbase + tid) * NTILES + blockIdx.y] = s;
        }
    }
}

// ---------------------------------------------------------------------------
// Kernel 2: knowledge partials — fp16 NT GEMM (this round's single variable,
// part 2; loader/compute verbatim from R14's know_h).
// ---------------------------------------------------------------------------
__global__ void __launch_bounds__(256, 2)
know_h()
{
    __shared__ uint32_t As[16][LDS_];
    __shared__ uint32_t Bs[16][LDS_];

    const int s = blockIdx.x, b = blockIdx.y;
    const int tid = threadIdx.x, lane = tid & 31, warp = tid >> 5;
    const int g = lane >> 2, tig = lane & 3;
    const int warpM = warp & 1, warpN = warp >> 1;
    const int mrow = warpM * 64, ncol = warpN * 32;

    const int am = tid >> 1;
    const __half* arow = g_kg + ((size_t)b * C + am) * N + (size_t)s * CHUNK;
    const __half* brow = g_v  + ((size_t)b * C + am) * N + (size_t)s * CHUNK;
    const int koff = (tid & 1) << 4;

    float acc[4][4][4] = {};
#pragma unroll 1
    for (int ss = 0; ss < CHUNK / 32; ss++) {
        stsT_raw_h(As, arow + ss * 32 + koff, tid);
        stsT_raw_h(Bs, brow + ss * 32 + koff, tid);
        __syncthreads();
        compute_slab_h(As, Bs, acc, mrow, ncol, g, tig);
        __syncthreads();
    }

    float* dst = g_part + ((size_t)b * SPLITK + s) * C * C;
#pragma unroll
    for (int mf = 0; mf < 4; mf++) {
        const int row = mrow + mf * 16 + g;
#pragma unroll
        for (int nf = 0; nf < 4; nf++) {
            const int col = ncol + nf * 8 + 2 * tig;
            *(float2*)(dst + (size_t)row * C + col)       = make_float2(acc[mf][nf][0], acc[mf][nf][1]);
            *(float2*)(dst + (size_t)(row + 8) * C + col) = make_float2(acc[mf][nf][2], acc[mf][nf][3]);
        }
    }
}

// ---------------------------------------------------------------------------
// Kernel 3: new_memory (R7 verbatim).
// ---------------------------------------------------------------------------
__global__ void mem_kernel(const float* __restrict__ prev, float* __restrict__ dout)
{
    const int b = blockIdx.x;
    const int tid = threadIdx.x;
    __shared__ float fs[128];
    if (tid < 128) {
        const float* p = g_fsum + ((size_t)b * C + tid) * NTILES;
        float s = 0.f;
        for (int i = 0; i < NTILES; i++) s += p[i];
        fs[tid] = s * (1.0f / (float)N);
    }
    __syncthreads();
    for (int e = tid; e < C * C; e += 256) {
        const int c = e >> 7;
        float a = fs[c] * prev[(size_t)b * C * C + e];
#pragma unroll
        for (int s2 = 0; s2 < SPLITK; s2++)
            a += g_part[((size_t)b * SPLITK + s2) * C * C + e];
        dout[OUT_ELEMS + (size_t)b * C * C + e] = a;
    }
}

// ---------------------------------------------------------------------------
// Kernel 4: E = Wp * M^T (R7 verbatim).
// ---------------------------------------------------------------------------
__global__ void __launch_bounds__(256, 2)
e_tc(const float* __restrict__ Wp, const float* __restrict__ dout)
{
    __shared__ uint32_t As[16][LDS_];
    __shared__ uint32_t Bs[16][LDS_];
    const int b = blockIdx.x;
    const float* M = dout + OUT_ELEMS + (size_t)b * C * C;

    const int tid = threadIdx.x, lane = tid & 31, warp = tid >> 5;
    const int g = lane >> 2, tig = lane & 3;
    const int warpM = warp & 1, warpN = warp >> 1;
    const int mrow = warpM * 64, ncol = warpN * 32;

    const int am = tid >> 1;
    const float* arow = Wp + (size_t)am * C;
    const float* brow = M  + (size_t)am * C;

    float acc[4][4][4] = {};
#pragma unroll 1
    for (int kk = 0; kk < C; kk += 16) {
        load_transpose(As, arow, kk, tid);
        load_transpose(Bs, brow, kk, tid);
        __syncthreads();
        compute_slab(As, Bs, acc, mrow, ncol, g, tig);
        __syncthreads();
    }

    float* dst = g_E + (size_t)b * C * C;
#pragma unroll
    for (int mf = 0; mf < 4; mf++) {
        const int row = mrow + mf * 16 + g;
#pragma unroll
        for (int nf = 0; nf < 4; nf++) {
            const int col = ncol + nf * 8 + 2 * tig;
            *(float2*)(dst + (size_t)row * C + col)       = make_float2(acc[mf][nf][0], acc[mf][nf][1]);
            *(float2*)(dst + (size_t)(row + 8) * C + col) = make_float2(acc[mf][nf][2], acc[mf][nf][3]);
        }
    }
}

// ---------------------------------------------------------------------------
// Kernel 5: F = E * Wq ; fb = E*bq + bp (R7 verbatim).
// ---------------------------------------------------------------------------
__global__ void __launch_bounds__(256, 2)
f_tc(const float* __restrict__ Wq, const float* __restrict__ bq,
     const float* __restrict__ bp)
{
    __shared__ uint32_t As[16][LDS_];
    __shared__ uint32_t Bs[16][LDS_];
    const int b = blockIdx.x;
    const float* E = g_E + (size_t)b * C * C;

    const int tid = threadIdx.x, lane = tid & 31, warp = tid >> 5;
    const int g = lane >> 2, tig = lane & 3;
    const int warpM = warp & 1, warpN = warp >> 1;
    const int mrow = warpM * 64, ncol = warpN * 32;

    const int am = tid >> 1;
    const float* arow = E + (size_t)am * C;

    float acc[4][4][4] = {};
#pragma unroll 1
    for (int kk = 0; kk < C; kk += 16) {
        load_transpose(As, arow, kk, tid);
        load_direct(Bs, Wq, C, 0, kk, tid);
        __syncthreads();
        compute_slab(As, Bs, acc, mrow, ncol, g, tig);
        __syncthreads();
    }

    float* dst = g_F + (size_t)b * C * C;
#pragma unroll
    for (int mf = 0; mf < 4; mf++) {
        const int row = mrow + mf * 16 + g;
#pragma unroll
        for (int nf = 0; nf < 4; nf++) {
            const int col = ncol + nf * 8 + 2 * tig;
            *(float2*)(dst + (size_t)row * C + col)       = make_float2(acc[mf][nf][0], acc[mf][nf][1]);
            *(float2*)(dst + (size_t)(row + 8) * C + col) = make_float2(acc[mf][nf][2], acc[mf][nf][3]);
        }
    }
    __syncthreads();
    if (tid < 128) {
        float s = bp[tid];
        const float* er = E + (size_t)tid * C;
        for (int c = 0; c < C; c++) s = fmaf(er[c], bq[c], s);
        g_fb[(size_t)b * C + tid] = s;
    }
}

// ---------------------------------------------------------------------------
// Kernel 6: out = F*x + fb + x (R14 fp16 verbatim — measured 99 µs).
// ---------------------------------------------------------------------------
__global__ void __launch_bounds__(256, 2)
out_h(const float* __restrict__ x, float* __restrict__ dout)
{
    __shared__ uint32_t As[16][LDS_];
    __shared__ uint32_t Bs[16][LDS_];

    const int n0 = blockIdx.x << 7;
    const int b  = blockIdx.y;
    const float* xb = x + (size_t)b * C * N;

    const int tid = threadIdx.x, lane = tid & 31, warp = tid >> 5;
    const int g = lane >> 2, tig = lane & 3;
    const int warpM = warp & 1, warpN = warp >> 1;
    const int mrow = warpM * 64, ncol = warpN * 32;

    const int am = tid >> 1;
    const float* myArow = g_F + (size_t)b * C * C + (size_t)am * C;

    float acc[4][4][4] = {};
#pragma unroll 1
    for (int kk = 0; kk < C; kk += 32) {
        stsT_h(As, myArow + kk + ((tid & 1) << 4), tid);
        stsD_h(Bs, xb + (size_t)kk * N + n0, N, tid);
        __syncthreads();
        compute_slab_h(As, Bs, acc, mrow, ncol, g, tig);
        __syncthreads();
    }

#pragma unroll
    for (int mf = 0; mf < 4; mf++) {
        const int o = mrow + mf * 16 + g;
        const float fb0 = g_fb[(size_t)b * C + o];
        const float fb1 = g_fb[(size_t)b * C + o + 8];
#pragma unroll
        for (int nf = 0; nf < 4; nf++) {
            const int col = n0 + ncol + nf * 8 + 2 * tig;
            float2 r0 = *(const float2*)(xb + (size_t)o * N + col);
            float2 r1 = *(const float2*)(xb + (size_t)(o + 8) * N + col);
            *(float2*)(dout + ((size_t)b * C + o) * N + col) =
                make_float2(acc[mf][nf][0] + fb0 + r0.x, acc[mf][nf][1] + fb0 + r0.y);
            *(float2*)(dout + ((size_t)b * C + o + 8) * N + col) =
                make_float2(acc[mf][nf][2] + fb1 + r1.x, acc[mf][nf][3] + fb1 + r1.y);
        }
    }
}

// ---------------------------------------------------------------------------
extern "C" void kernel_launch(void* const* d_in, const int* in_sizes, int n_in,
                              void* d_out, int out_size)
{
    const float* x    = (const float*)d_in[0];
    const float* prev = (const float*)d_in[1];
    const float* Wq   = (const float*)d_in[2];
    const float* bq   = (const float*)d_in[3];
    const float* Wk   = (const float*)d_in[4];
    const float* bk   = (const float*)d_in[5];
    const float* Wv   = (const float*)d_in[6];
    const float* bv   = (const float*)d_in[7];
    const float* Wg   = (const float*)d_in[8];
    const float* bg   = (const float*)d_in[9];
    const float* Wp   = (const float*)d_in[10];
    const float* bp   = (const float*)d_in[11];
    float* out = (float*)d_out;

    proj_tc<<<dim3(4, NTILES, BATCH), 256>>>(x, Wk, bk, Wv, bv, Wg, bg);
    know_h<<<dim3(SPLITK, BATCH), 256>>>();
    mem_kernel<<<BATCH, 256>>>(prev, out);
    e_tc<<<BATCH, 256>>>(Wp, out);
    f_tc<<<BATCH, 256>>>(Wq, bq, bp);
    out_h<<<dim3(NTILES, BATCH), 256>>>(x, out);
}

// round 17
// speedup vs baseline: 1.8830x; 1.2173x over previous
#include <cuda_runtime.h>
#include <cuda_fp16.h>
#include <stdint.h>
#include <math.h>

static constexpr int BATCH  = 16;
static constexpr int C      = 128;
static constexpr int N      = 16384;
static constexpr int SPLITK = 16;
static constexpr int CHUNK  = N / SPLITK;    // 1024
static constexpr int NTILES = N / 128;       // 128
static constexpr size_t OUT_ELEMS = (size_t)BATCH * C * N;
static constexpr int LDS_ = 136;             // padded smem stride (words)

// ---------------- scratch (static device globals; no allocations) ----------
__device__ __half g_kg [(size_t)BATCH * C * N];          // fp16
__device__ __half g_v  [(size_t)BATCH * C * N];          // fp16
__device__ float g_part[(size_t)BATCH * SPLITK * C * C];
__device__ float g_fsum[(size_t)BATCH * C * NTILES];     // [b][c][tile]
__device__ float g_E   [(size_t)BATCH * C * C];
__device__ float g_F   [(size_t)BATCH * C * C];
__device__ float g_fb  [(size_t)BATCH * C];

__device__ __forceinline__ float sigmoidf_(float v) { return 1.0f / (1.0f + __expf(-v)); }

__device__ __forceinline__ uint32_t f2tf(float f) {
    uint32_t u; asm("cvt.rna.tf32.f32 %0, %1;" : "=r"(u) : "f"(f)); return u;
}
__device__ __forceinline__ uint32_t pk2(float a, float b) {
    __half2 h = __floats2half2_rn(a, b);
    return *(uint32_t*)&h;
}

__device__ __forceinline__ void mma_tf32(float c[4],
    uint32_t a0, uint32_t a1, uint32_t a2, uint32_t a3, uint32_t b0, uint32_t b1)
{
    asm volatile(
        "mma.sync.aligned.m16n8k8.row.col.f32.tf32.tf32.f32 "
        "{%0,%1,%2,%3}, {%4,%5,%6,%7}, {%8,%9}, {%0,%1,%2,%3};\n"
        : "+f"(c[0]), "+f"(c[1]), "+f"(c[2]), "+f"(c[3])
        : "r"(a0), "r"(a1), "r"(a2), "r"(a3), "r"(b0), "r"(b1));
}
__device__ __forceinline__ void mma_f16(float c[4],
    uint32_t a0, uint32_t a1, uint32_t a2, uint32_t a3, uint32_t b0, uint32_t b1)
{
    asm volatile(
        "mma.sync.aligned.m16n8k16.row.col.f32.f16.f16.f32 "
        "{%0,%1,%2,%3}, {%4,%5,%6,%7}, {%8,%9}, {%0,%1,%2,%3};\n"
        : "+f"(c[0]), "+f"(c[1]), "+f"(c[2]), "+f"(c[3])
        : "r"(a0), "r"(a1), "r"(a2), "r"(a3), "r"(b0), "r"(b1));
}

// ================= tf32 machinery (R7 measured-best, verbatim) ==============
__device__ __forceinline__ void load_transpose(uint32_t (*S)[LDS_], const float* myrow,
                                               int kbase, int tid)
{
    const int m = tid >> 1, koff = (tid & 1) << 3;
    const float* p = myrow + kbase + koff;
    float4 u = *(const float4*)p;
    float4 v = *(const float4*)(p + 4);
    S[koff + 0][m] = f2tf(u.x); S[koff + 1][m] = f2tf(u.y);
    S[koff + 2][m] = f2tf(u.z); S[koff + 3][m] = f2tf(u.w);
    S[koff + 4][m] = f2tf(v.x); S[koff + 5][m] = f2tf(v.y);
    S[koff + 6][m] = f2tf(v.z); S[koff + 7][m] = f2tf(v.w);
}
__device__ __forceinline__ void load_direct(uint32_t (*S)[LDS_], const float* src,
                                            size_t ld, int n0, int kbase, int tid)
{
    const int kb = tid >> 4, nb = (tid & 15) << 3;
    const float* p = src + (size_t)(kbase + kb) * ld + n0 + nb;
    float4 u = *(const float4*)p;
    float4 v = *(const float4*)(p + 4);
    *(uint4*)&S[kb][nb]     = make_uint4(f2tf(u.x), f2tf(u.y), f2tf(u.z), f2tf(u.w));
    *(uint4*)&S[kb][nb + 4] = make_uint4(f2tf(v.x), f2tf(v.y), f2tf(v.z), f2tf(v.w));
}
__device__ __forceinline__ void compute_slab(const uint32_t (*As)[LDS_], const uint32_t (*Bs)[LDS_],
                                             float acc[4][4][4], int mrow, int ncol, int g, int tig)
{
#pragma unroll
    for (int ks = 0; ks < 2; ks++) {
        uint32_t a[4][4], b[4][2];
#pragma unroll
        for (int mf = 0; mf < 4; mf++) {
            const int m = mrow + mf * 16 + g;
            a[mf][0] = As[ks * 8 + tig][m];
            a[mf][1] = As[ks * 8 + tig][m + 8];
            a[mf][2] = As[ks * 8 + tig + 4][m];
            a[mf][3] = As[ks * 8 + tig + 4][m + 8];
        }
#pragma unroll
        for (int nf = 0; nf < 4; nf++) {
            const int n = ncol + nf * 8 + g;
            b[nf][0] = Bs[ks * 8 + tig][n];
            b[nf][1] = Bs[ks * 8 + tig + 4][n];
        }
#pragma unroll
        for (int mf = 0; mf < 4; mf++)
#pragma unroll
            for (int nf = 0; nf < 4; nf++)
                mma_tf32(acc[mf][nf], a[mf][0], a[mf][1], a[mf][2], a[mf][3],
                         b[nf][0], b[nf][1]);
    }
}

// ================= fp16 machinery (R14; out_h measured 99 µs) ===============
__device__ __forceinline__ void stsT_h(uint32_t (*S)[LDS_], const float* p, int tid) {
    const int m = tid >> 1, ko = (tid & 1) << 3;
    float4 u0 = *(const float4*)(p);
    float4 u1 = *(const float4*)(p + 4);
    float4 u2 = *(const float4*)(p + 8);
    float4 u3 = *(const float4*)(p + 12);
    S[ko + 0][m] = pk2(u0.x, u0.y); S[ko + 1][m] = pk2(u0.z, u0.w);
    S[ko + 2][m] = pk2(u1.x, u1.y); S[ko + 3][m] = pk2(u1.z, u1.w);
    S[ko + 4][m] = pk2(u2.x, u2.y); S[ko + 5][m] = pk2(u2.z, u2.w);
    S[ko + 6][m] = pk2(u3.x, u3.y); S[ko + 7][m] = pk2(u3.z, u3.w);
}
__device__ __forceinline__ void stsT_raw_h(uint32_t (*S)[LDS_], const __half* p, int tid) {
    const int m = tid >> 1, ko = (tid & 1) << 3;
    uint4 a = *(const uint4*)(p);
    uint4 b = *(const uint4*)(p + 8);
    S[ko + 0][m] = a.x; S[ko + 1][m] = a.y; S[ko + 2][m] = a.z; S[ko + 3][m] = a.w;
    S[ko + 4][m] = b.x; S[ko + 5][m] = b.y; S[ko + 6][m] = b.z; S[ko + 7][m] = b.w;
}
__device__ __forceinline__ void stsD_h(uint32_t (*S)[LDS_], const float* src, size_t ld, int tid) {
    const int kb = tid >> 4, nb = (tid & 15) << 3;
    const float* r0 = src + (size_t)(2 * kb) * ld + nb;
    const float* r1 = r0 + ld;
    float4 a0 = *(const float4*)r0, a1 = *(const float4*)(r0 + 4);
    float4 b0 = *(const float4*)r1, b1 = *(const float4*)(r1 + 4);
    *(uint4*)&S[kb][nb]     = make_uint4(pk2(a0.x, b0.x), pk2(a0.y, b0.y),
                                         pk2(a0.z, b0.z), pk2(a0.w, b0.w));
    *(uint4*)&S[kb][nb + 4] = make_uint4(pk2(a1.x, b1.x), pk2(a1.y, b1.y),
                                         pk2(a1.z, b1.z), pk2(a1.w, b1.w));
}
__device__ __forceinline__ void compute_slab_h(const uint32_t (*As)[LDS_], const uint32_t (*Bs)[LDS_],
                                               float acc[4][4][4], int mrow, int ncol, int g, int tig)
{
#pragma unroll
    for (int ks = 0; ks < 2; ks++) {
        uint32_t a[4][4], b[4][2];
#pragma unroll
        for (int mf = 0; mf < 4; mf++) {
            const int m = mrow + mf * 16 + g;
            a[mf][0] = As[ks * 8 + tig][m];     a[mf][1] = As[ks * 8 + tig][m + 8];
            a[mf][2] = As[ks * 8 + tig + 4][m]; a[mf][3] = As[ks * 8 + tig + 4][m + 8];
        }
#pragma unroll
        for (int nf = 0; nf < 4; nf++) {
            const int n = ncol + nf * 8 + g;
            b[nf][0] = Bs[ks * 8 + tig][n]; b[nf][1] = Bs[ks * 8 + tig + 4][n];
        }
#pragma unroll
        for (int mf = 0; mf < 4; mf++)
#pragma unroll
            for (int nf = 0; nf < 4; nf++)
                mma_f16(acc[mf][nf], a[mf][0], a[mf][1], a[mf][2], a[mf][3],
                        b[nf][0], b[nf][1]);
    }
}

// ---------------------------------------------------------------------------
// Kernel 1: fused projections — fp16 mma (this round's single variable;
// R14 proj_h verbatim except g_fsum store uses R16's [b][c][tile] layout).
// ---------------------------------------------------------------------------
__global__ void __launch_bounds__(256, 2)
proj_h(const float* __restrict__ x,
       const float* __restrict__ Wk, const float* __restrict__ bk,
       const float* __restrict__ Wv, const float* __restrict__ bv,
       const float* __restrict__ Wg, const float* __restrict__ bg)
{
    __shared__ uint32_t As[16][LDS_];
    __shared__ uint32_t Bs[16][LDS_];
    __shared__ float red[64][4];

    const int idx   = blockIdx.x;
    const int type  = idx >> 1;
    const int cbase = (idx & 1) * 64;
    const int n0    = blockIdx.y << 7;
    const int b     = blockIdx.z;

    const float *W1, *W2, *b1, *b2;
    if (type == 0) { W1 = Wk; b1 = bk; W2 = Wg + C * C; b2 = bg + C; }
    else           { W1 = Wv; b1 = bv; W2 = Wg;         b2 = bg;     }

    const int tid = threadIdx.x, lane = tid & 31, warp = tid >> 5;
    const int g = lane >> 2, tig = lane & 3;
    const int warpM = warp & 1, warpN = warp >> 1;
    const int mrow = warpM * 64, ncol = warpN * 32;

    const int am = tid >> 1;
    const int agrp = am >> 4, awi = am & 15;
    const int ach = cbase + agrp * 8 + (awi & 7);
    const float* myArow = ((awi < 8) ? W1 : W2) + (size_t)ach * C;
    const float* xb = x + (size_t)b * C * N;

    float acc[4][4][4] = {};
#pragma unroll 1
    for (int kk = 0; kk < C; kk += 32) {
        stsT_h(As, myArow + kk + ((tid & 1) << 4), tid);
        stsD_h(Bs, xb + (size_t)kk * N + n0, N, tid);
        __syncthreads();
        compute_slab_h(As, Bs, acc, mrow, ncol, g, tig);
        __syncthreads();
    }

    if (type == 0) {
#pragma unroll
        for (int mf = 0; mf < 4; mf++) {
            const int ch = cbase + (warpM * 4 + mf) * 8 + g;
            const float bb1 = b1[ch], bb2 = b2[ch];
            __half* dst = g_kg + ((size_t)b * C + ch) * N + n0 + ncol + 2 * tig;
#pragma unroll
            for (int nf = 0; nf < 4; nf++) {
                float o0 = (acc[mf][nf][0] + bb1) * sigmoidf_(acc[mf][nf][2] + bb2);
                float o1 = (acc[mf][nf][1] + bb1) * sigmoidf_(acc[mf][nf][3] + bb2);
                *(uint32_t*)(dst + nf * 8) = pk2(o0, o1);
            }
        }
    } else {
#pragma unroll
        for (int mf = 0; mf < 4; mf++) {
            const int ch = cbase + (warpM * 4 + mf) * 8 + g;
            const float bb1 = b1[ch], bb2 = b2[ch];
            __half* dv = g_v + ((size_t)b * C + ch) * N + n0 + ncol + 2 * tig;
            float sm = 0.f;
#pragma unroll
            for (int nf = 0; nf < 4; nf++) {
                *(uint32_t*)(dv + nf * 8) = pk2(acc[mf][nf][0] + bb1,
                                                acc[mf][nf][1] + bb1);
                sm += sigmoidf_(acc[mf][nf][2] + bb2) + sigmoidf_(acc[mf][nf][3] + bb2);
            }
            sm += __shfl_xor_sync(0xffffffffu, sm, 1);
            sm += __shfl_xor_sync(0xffffffffu, sm, 2);
            if (tig == 0) red[(warpM * 4 + mf) * 8 + g][warpN] = sm;
        }
        __syncthreads();
        if (tid < 64) {
            float sm = red[tid][0] + red[tid][1] + red[tid][2] + red[tid][3];
            g_fsum[((size_t)b * C + cbase + tid) * NTILES + blockIdx.y] = sm;
        }
    }
}

// ---------------------------------------------------------------------------
// Kernel 2: knowledge partials — fp16 NT GEMM (R16 verbatim).
// ---------------------------------------------------------------------------
__global__ void __launch_bounds__(256, 2)
know_h()
{
    __shared__ uint32_t As[16][LDS_];
    __shared__ uint32_t Bs[16][LDS_];

    const int s = blockIdx.x, b = blockIdx.y;
    const int tid = threadIdx.x, lane = tid & 31, warp = tid >> 5;
    const int g = lane >> 2, tig = lane & 3;
    const int warpM = warp & 1, warpN = warp >> 1;
    const int mrow = warpM * 64, ncol = warpN * 32;

    const int am = tid >> 1;
    const __half* arow = g_kg + ((size_t)b * C + am) * N + (size_t)s * CHUNK;
    const __half* brow = g_v  + ((size_t)b * C + am) * N + (size_t)s * CHUNK;
    const int koff = (tid & 1) << 4;

    float acc[4][4][4] = {};
#pragma unroll 1
    for (int ss = 0; ss < CHUNK / 32; ss++) {
        stsT_raw_h(As, arow + ss * 32 + koff, tid);
        stsT_raw_h(Bs, brow + ss * 32 + koff, tid);
        __syncthreads();
        compute_slab_h(As, Bs, acc, mrow, ncol, g, tig);
        __syncthreads();
    }

    float* dst = g_part + ((size_t)b * SPLITK + s) * C * C;
#pragma unroll
    for (int mf = 0; mf < 4; mf++) {
        const int row = mrow + mf * 16 + g;
#pragma unroll
        for (int nf = 0; nf < 4; nf++) {
            const int col = ncol + nf * 8 + 2 * tig;
            *(float2*)(dst + (size_t)row * C + col)       = make_float2(acc[mf][nf][0], acc[mf][nf][1]);
            *(float2*)(dst + (size_t)(row + 8) * C + col) = make_float2(acc[mf][nf][2], acc[mf][nf][3]);
        }
    }
}

// ---------------------------------------------------------------------------
// Kernel 3: new_memory (R7 verbatim).
// ---------------------------------------------------------------------------
__global__ void mem_kernel(const float* __restrict__ prev, float* __restrict__ dout)
{
    const int b = blockIdx.x;
    const int tid = threadIdx.x;
    __shared__ float fs[128];
    if (tid < 128) {
        const float* p = g_fsum + ((size_t)b * C + tid) * NTILES;
        float s = 0.f;
        for (int i = 0; i < NTILES; i++) s += p[i];
        fs[tid] = s * (1.0f / (float)N);
    }
    __syncthreads();
    for (int e = tid; e < C * C; e += 256) {
        const int c = e >> 7;
        float a = fs[c] * prev[(size_t)b * C * C + e];
#pragma unroll
        for (int s2 = 0; s2 < SPLITK; s2++)
            a += g_part[((size_t)b * SPLITK + s2) * C * C + e];
        dout[OUT_ELEMS + (size_t)b * C * C + e] = a;
    }
}

// ---------------------------------------------------------------------------
// Kernel 4: E = Wp * M^T (R7 verbatim).
// ---------------------------------------------------------------------------
__global__ void __launch_bounds__(256, 2)
e_tc(const float* __restrict__ Wp, const float* __restrict__ dout)
{
    __shared__ uint32_t As[16][LDS_];
    __shared__ uint32_t Bs[16][LDS_];
    const int b = blockIdx.x;
    const float* M = dout + OUT_ELEMS + (size_t)b * C * C;

    const int tid = threadIdx.x, lane = tid & 31, warp = tid >> 5;
    const int g = lane >> 2, tig = lane & 3;
    const int warpM = warp & 1, warpN = warp >> 1;
    const int mrow = warpM * 64, ncol = warpN * 32;

    const int am = tid >> 1;
    const float* arow = Wp + (size_t)am * C;
    const float* brow = M  + (size_t)am * C;

    float acc[4][4][4] = {};
#pragma unroll 1
    for (int kk = 0; kk < C; kk += 16) {
        load_transpose(As, arow, kk, tid);
        load_transpose(Bs, brow, kk, tid);
        __syncthreads();
        compute_slab(As, Bs, acc, mrow, ncol, g, tig);
        __syncthreads();
    }

    float* dst = g_E + (size_t)b * C * C;
#pragma unroll
    for (int mf = 0; mf < 4; mf++) {
        const int row = mrow + mf * 16 + g;
#pragma unroll
        for (int nf = 0; nf < 4; nf++) {
            const int col = ncol + nf * 8 + 2 * tig;
            *(float2*)(dst + (size_t)row * C + col)       = make_float2(acc[mf][nf][0], acc[mf][nf][1]);
            *(float2*)(dst + (size_t)(row + 8) * C + col) = make_float2(acc[mf][nf][2], acc[mf][nf][3]);
        }
    }
}

// ---------------------------------------------------------------------------
// Kernel 5: F = E * Wq ; fb = E*bq + bp (R7 verbatim).
// ---------------------------------------------------------------------------
__global__ void __launch_bounds__(256, 2)
f_tc(const float* __restrict__ Wq, const float* __restrict__ bq,
     const float* __restrict__ bp)
{
    __shared__ uint32_t As[16][LDS_];
    __shared__ uint32_t Bs[16][LDS_];
    const int b = blockIdx.x;
    const float* E = g_E + (size_t)b * C * C;

    const int tid = threadIdx.x, lane = tid & 31, warp = tid >> 5;
    const int g = lane >> 2, tig = lane & 3;
    const int warpM = warp & 1, warpN = warp >> 1;
    const int mrow = warpM * 64, ncol = warpN * 32;

    const int am = tid >> 1;
    const float* arow = E + (size_t)am * C;

    float acc[4][4][4] = {};
#pragma unroll 1
    for (int kk = 0; kk < C; kk += 16) {
        load_transpose(As, arow, kk, tid);
        load_direct(Bs, Wq, C, 0, kk, tid);
        __syncthreads();
        compute_slab(As, Bs, acc, mrow, ncol, g, tig);
        __syncthreads();
    }

    float* dst = g_F + (size_t)b * C * C;
#pragma unroll
    for (int mf = 0; mf < 4; mf++) {
        const int row = mrow + mf * 16 + g;
#pragma unroll
        for (int nf = 0; nf < 4; nf++) {
            const int col = ncol + nf * 8 + 2 * tig;
            *(float2*)(dst + (size_t)row * C + col)       = make_float2(acc[mf][nf][0], acc[mf][nf][1]);
            *(float2*)(dst + (size_t)(row + 8) * C + col) = make_float2(acc[mf][nf][2], acc[mf][nf][3]);
        }
    }
    __syncthreads();
    if (tid < 128) {
        float s = bp[tid];
        const float* er = E + (size_t)tid * C;
        for (int c = 0; c < C; c++) s = fmaf(er[c], bq[c], s);
        g_fb[(size_t)b * C + tid] = s;
    }
}

// ---------------------------------------------------------------------------
// Kernel 6: out = F*x + fb + x (R14 fp16 verbatim — measured 99 µs).
// ---------------------------------------------------------------------------
__global__ void __launch_bounds__(256, 2)
out_h(const float* __restrict__ x, float* __restrict__ dout)
{
    __shared__ uint32_t As[16][LDS_];
    __shared__ uint32_t Bs[16][LDS_];

    const int n0 = blockIdx.x << 7;
    const int b  = blockIdx.y;
    const float* xb = x + (size_t)b * C * N;

    const int tid = threadIdx.x, lane = tid & 31, warp = tid >> 5;
    const int g = lane >> 2, tig = lane & 3;
    const int warpM = warp & 1, warpN = warp >> 1;
    const int mrow = warpM * 64, ncol = warpN * 32;

    const int am = tid >> 1;
    const float* myArow = g_F + (size_t)b * C * C + (size_t)am * C;

    float acc[4][4][4] = {};
#pragma unroll 1
    for (int kk = 0; kk < C; kk += 32) {
        stsT_h(As, myArow + kk + ((tid & 1) << 4), tid);
        stsD_h(Bs, xb + (size_t)kk * N + n0, N, tid);
        __syncthreads();
        compute_slab_h(As, Bs, acc, mrow, ncol, g, tig);
        __syncthreads();
    }

#pragma unroll
    for (int mf = 0; mf < 4; mf++) {
        const int o = mrow + mf * 16 + g;
        const float fb0 = g_fb[(size_t)b * C + o];
        const float fb1 = g_fb[(size_t)b * C + o + 8];
#pragma unroll
        for (int nf = 0; nf < 4; nf++) {
            const int col = n0 + ncol + nf * 8 + 2 * tig;
            float2 r0 = *(const float2*)(xb + (size_t)o * N + col);
            float2 r1 = *(const float2*)(xb + (size_t)(o + 8) * N + col);
            *(float2*)(dout + ((size_t)b * C + o) * N + col) =
                make_float2(acc[mf][nf][0] + fb0 + r0.x, acc[mf][nf][1] + fb0 + r0.y);
            *(float2*)(dout + ((size_t)b * C + o + 8) * N + col) =
                make_float2(acc[mf][nf][2] + fb1 + r1.x, acc[mf][nf][3] + fb1 + r1.y);
        }
    }
}

// ---------------------------------------------------------------------------
extern "C" void kernel_launch(void* const* d_in, const int* in_sizes, int n_in,
                              void* d_out, int out_size)
{
    const float* x    = (const float*)d_in[0];
    const float* prev = (const float*)d_in[1];
    const float* Wq   = (const float*)d_in[2];
    const float* bq   = (const float*)d_in[3];
    const float* Wk   = (const float*)d_in[4];
    const float* bk   = (const float*)d_in[5];
    const float* Wv   = (const float*)d_in[6];
    const float* bv   = (const float*)d_in[7];
    const float* Wg   = (const float*)d_in[8];
    const float* bg   = (const float*)d_in[9];
    const float* Wp   = (const float*)d_in[10];
    const float* bp   = (const float*)d_in[11];
    float* out = (float*)d_out;

    proj_h<<<dim3(4, NTILES, BATCH), 256>>>(x, Wk, bk, Wv, bv, Wg, bg);
    know_h<<<dim3(SPLITK, BATCH), 256>>>();
    mem_kernel<<<BATCH, 256>>>(prev, out);
    e_tc<<<BATCH, 256>>>(Wp, out);
    f_tc<<<BATCH, 256>>>(Wq, bq, bp);
    out_h<<<dim3(NTILES, BATCH), 256>>>(x, out);
}